// round 7
// baseline (speedup 1.0000x reference)
#include <cuda_runtime.h>
#include <cuda_bf16.h>

#define NN 8192
#define NV4 (NN / 4)                  // float4 per row = 2048
#define TOTV4 (NN * (NN / 4))         // total float4 = 16,777,216 = 2^24
#define BLOCKS 1216                   // 8 CTAs/SM x 152 SMs (GB300) = one balanced wave
#define THREADS 256
#define STRIDE (BLOCKS * THREADS)     // 311,296

__device__ double   g_acc;            // statically zero-initialized
__device__ unsigned g_count;          // statically zero-initialized

#define LOG2E 1.4426950408889634f
#define LN2   0.6931471805599453f

// softplus in log2 domain: sp2(y) = max(y,0) + log2(1 + 2^(-|y|)); softplus = ln2*sp2
__device__ __forceinline__ float sp2(float y) {
    float e = exp2f(-fabsf(y));       // MUFU EX2
    float l = __log2f(1.0f + e);      // MUFU LG2
    return fmaxf(y, 0.0f) + l;
}

__device__ __forceinline__ float block_reduce(float v) {
    #pragma unroll
    for (int off = 16; off > 0; off >>= 1)
        v += __shfl_down_sync(0xFFFFFFFFu, v, off);

    __shared__ float warp_sums[THREADS / 32];
    int lane = threadIdx.x & 31;
    int wid  = threadIdx.x >> 5;
    if (lane == 0) warp_sums[wid] = v;
    __syncthreads();

    float s = 0.0f;
    if (wid == 0) {
        s = (lane < (THREADS >> 5)) ? warp_sums[lane] : 0.0f;
        #pragma unroll
        for (int off = 4; off > 0; off >>= 1)
            s += __shfl_down_sync(0xFFFFFFFFu, s, off);
    }
    return s;   // valid in thread 0
}

__global__ void __launch_bounds__(THREADS)
bt_fused_kernel(const float4* __restrict__ W4,
                const float*  __restrict__ Ws,     // same buffer, scalar view
                const float*  __restrict__ betas,
                float* __restrict__ out) {
    const float4* __restrict__ B4 = reinterpret_cast<const float4*>(betas);

    float local = 0.0f;
    int idx = blockIdx.x * THREADS + threadIdx.x;

    // ---- main: sum over ALL 64M entries (diagonal corrected below) ----
    #pragma unroll 8
    for (int v = idx; v < TOTV4; v += STRIDE) {
        int row  = v >> 11;           // warp-uniform (32 float4 per warp span one row)
        int colv = v & (NV4 - 1);

        float  bi   = betas[row];     // L1-resident (32 KB)
        float  nbiL = -bi * LOG2E;
        float4 w    = __ldcs(&W4[v]); // streaming read-once: evict-first
        float4 bj   = B4[colv];       // L1-resident

        // y = (bj - bi)*log2e as one FFMA per element
        float t0 = w.x * sp2(fmaf(bj.x, LOG2E, nbiL));
        float t1 = w.y * sp2(fmaf(bj.y, LOG2E, nbiL));
        float t2 = w.z * sp2(fmaf(bj.z, LOG2E, nbiL));
        float t3 = w.w * sp2(fmaf(bj.w, LOG2E, nbiL));

        local += (t0 + t1) + (t2 + t3);
    }

    // ---- diag correction folded into block 0: subtract sum_i W[i,i] (sp2(0)=1) ----
    if (blockIdx.x == 0) {
        #pragma unroll
        for (int k = 0; k < NN / THREADS; ++k) {
            int i = k * THREADS + threadIdx.x;
            local -= __ldcs(&Ws[(size_t)i * (NN + 1)]);
        }
    }

    float s = block_reduce(local);

    if (threadIdx.x == 0) {
        atomicAdd(&g_acc, (double)s);
        __threadfence();
        unsigned ticket = atomicAdd(&g_count, 1u);
        if (ticket == BLOCKS - 1) {
            __threadfence();                       // acquire all g_acc contributions
            out[0]  = (float)(g_acc * (double)LN2);
            g_acc   = 0.0;                         // reset for next graph replay
            g_count = 0u;
        }
    }
}

extern "C" void kernel_launch(void* const* d_in, const int* in_sizes, int n_in,
                              void* d_out, int out_size) {
    const float* W     = (const float*)d_in[0];   // win_matrix [N,N] fp32
    const float* betas = (const float*)d_in[1];   // betas [N] fp32
    float* out = (float*)d_out;

    bt_fused_kernel<<<BLOCKS, THREADS>>>((const float4*)W, W, betas, out);
}

// round 14
// speedup vs baseline: 1.0962x; 1.0962x over previous
#include <cuda_runtime.h>
#include <cuda_bf16.h>

#define NN 8192
#define NV4 (NN / 4)                  // float4 per row = 2048
#define GROUPS 152                    // one group per SM
#define SUBS 8                        // 8 blocks cover one row: 8*256 = 2048 float4
#define BLOCKS (GROUPS * SUBS)        // 1216 = 8 CTAs/SM x 152 SMs, one wave
#define THREADS 256

__device__ double   g_acc;            // statically zero-initialized
__device__ unsigned g_count;          // statically zero-initialized

#define LOG2E 1.4426950408889634f
#define LN2   0.6931471805599453f

// softplus in log2 domain: sp2(y) = max(y,0) + log2(1 + 2^(-|y|)); softplus = ln2*sp2
__device__ __forceinline__ float sp2(float y) {
    float e = exp2f(-fabsf(y));       // MUFU EX2 (input modifiers free)
    float l = __log2f(1.0f + e);      // MUFU LG2
    return fmaxf(y, 0.0f) + l;
}

__device__ __forceinline__ float block_reduce(float v) {
    #pragma unroll
    for (int off = 16; off > 0; off >>= 1)
        v += __shfl_down_sync(0xFFFFFFFFu, v, off);

    __shared__ float warp_sums[THREADS / 32];
    int lane = threadIdx.x & 31;
    int wid  = threadIdx.x >> 5;
    if (lane == 0) warp_sums[wid] = v;
    __syncthreads();

    float s = 0.0f;
    if (wid == 0) {
        s = (lane < (THREADS >> 5)) ? warp_sums[lane] : 0.0f;
        #pragma unroll
        for (int off = 4; off > 0; off >>= 1)
            s += __shfl_down_sync(0xFFFFFFFFu, s, off);
    }
    return s;   // valid in thread 0
}

__global__ void __launch_bounds__(THREADS)
bt_fused_kernel(const float4* __restrict__ W4,
                const float*  __restrict__ Ws,     // same buffer, scalar view
                const float*  __restrict__ betas,
                float* __restrict__ out) {
    const int g    = blockIdx.x >> 3;                       // 0..151
    const int colv = ((blockIdx.x & 7) << 8) | threadIdx.x; // fixed column chunk

    // column betas: loaded ONCE, prescaled to log2 domain, register-resident
    float4 bj = reinterpret_cast<const float4*>(betas)[colv];
    const float bjx = bj.x * LOG2E, bjy = bj.y * LOG2E;
    const float bjz = bj.z * LOG2E, bjw = bj.w * LOG2E;

    float acc0 = 0.0f, acc1 = 0.0f;

    // rows g, g+152, ... : W access coalesced (block reads contiguous 4KB per row)
    #pragma unroll 4
    for (int r = g; r < NN; r += GROUPS) {
        float  nbiL = -__ldg(&betas[r]) * LOG2E;            // warp-uniform, L1-hit
        float4 w    = __ldcs(&W4[((size_t)r << 11) + colv]); // streaming read-once

        acc0 = fmaf(w.x, sp2(bjx + nbiL), acc0);
        acc0 = fmaf(w.y, sp2(bjy + nbiL), acc0);
        acc1 = fmaf(w.z, sp2(bjz + nbiL), acc1);
        acc1 = fmaf(w.w, sp2(bjw + nbiL), acc1);
    }

    float local = acc0 + acc1;

    // diag correction, distributed: sub==0 block subtracts its group's diagonal
    // (sp2(0) = 1 in log2 domain, so correction is just -W[r,r])
    if ((blockIdx.x & 7) == 0) {
        int r = g + threadIdx.x * GROUPS;                   // thread k -> row g+k*152
        if (r < NN)
            local -= __ldg(&Ws[(size_t)r * (NN + 1)]);
    }

    float s = block_reduce(local);

    if (threadIdx.x == 0) {
        atomicAdd(&g_acc, (double)s);
        __threadfence();
        unsigned ticket = atomicAdd(&g_count, 1u);
        if (ticket == BLOCKS - 1) {
            __threadfence();                       // acquire all g_acc contributions
            out[0]  = (float)(g_acc * (double)LN2);
            g_acc   = 0.0;                         // reset for next graph replay
            g_count = 0u;
        }
    }
}

extern "C" void kernel_launch(void* const* d_in, const int* in_sizes, int n_in,
                              void* d_out, int out_size) {
    const float* W     = (const float*)d_in[0];   // win_matrix [N,N] fp32
    const float* betas = (const float*)d_in[1];   // betas [N] fp32
    float* out = (float*)d_out;

    bt_fused_kernel<<<BLOCKS, THREADS>>>((const float4*)W, W, betas, out);
}